// round 8
// baseline (speedup 1.0000x reference)
#include <cuda_runtime.h>
#include <math.h>

#define BB 4
#define NN 1024
#define FF 512
#define EE 32
#define HH 8
#define HD 64
#define MM (BB*NN)   // 4096

// ---- scratch (static device globals: allowed; runtime alloc is not) ----
__device__ unsigned g_Qh[MM*FF], g_Ql[MM*FF];
__device__ unsigned g_Kh[MM*FF], g_Kl[MM*FF];
__device__ unsigned g_Vh[MM*FF], g_Vl[MM*FF];
__device__ float    g_AO[MM*FF];
__device__ float    g_bias[(size_t)BB*HH*NN*NN];   // [b][h][q][k], mask folded in

// ============================================================================
// helpers: tf32 split + mma, packed f32x2 fma
// ============================================================================
__device__ __forceinline__ void split_tf32(float x, unsigned& hi, unsigned& lo) {
    asm("cvt.rna.tf32.f32 %0, %1;" : "=r"(hi) : "f"(x));
    float r = x - __uint_as_float(hi);
    asm("cvt.rna.tf32.f32 %0, %1;" : "=r"(lo) : "f"(r));
}

__device__ __forceinline__ void mma_tf32(float (&d)[4], const unsigned (&a)[4],
                                         unsigned b0, unsigned b1) {
    asm volatile(
        "mma.sync.aligned.m16n8k8.row.col.f32.tf32.tf32.f32 "
        "{%0,%1,%2,%3}, {%4,%5,%6,%7}, {%8,%9}, {%0,%1,%2,%3};\n"
        : "+f"(d[0]), "+f"(d[1]), "+f"(d[2]), "+f"(d[3])
        : "r"(a[0]), "r"(a[1]), "r"(a[2]), "r"(a[3]), "r"(b0), "r"(b1));
}

__device__ __forceinline__ unsigned long long pk2(float x, float y) {
    unsigned long long r;
    asm("mov.b64 %0, {%1,%2};" : "=l"(r) : "f"(x), "f"(y));
    return r;
}
__device__ __forceinline__ float2 upk2(unsigned long long v) {
    float x, y;
    asm("mov.b64 {%0,%1}, %2;" : "=f"(x), "=f"(y) : "l"(v));
    return make_float2(x, y);
}
__device__ __forceinline__ unsigned long long fma2(unsigned long long a,
                                                   unsigned long long b,
                                                   unsigned long long c) {
    unsigned long long d;
    asm("fma.rn.f32x2 %0, %1, %2, %3;" : "=l"(d) : "l"(a), "l"(b), "l"(c));
    return d;
}

// ============================================================================
// 3xTF32 GEMM (NT): C[M,512] = A[M,512] @ W[512,512]^T + bias.
// mode 0 (QKV): writes tf32 (hi,lo) split arrays; z==0 (Q) pre-scaled 0.125.
// mode 1 (O-proj): writes float C.
// ============================================================================
__global__ __launch_bounds__(256) void gemm_tf32x3(
    const float* __restrict__ A,
    const float* __restrict__ W0, const float* __restrict__ W1, const float* __restrict__ W2,
    const float* __restrict__ b0p, const float* __restrict__ b1p, const float* __restrict__ b2p,
    float* __restrict__ C,
    unsigned* __restrict__ H0, unsigned* __restrict__ L0,
    unsigned* __restrict__ H1, unsigned* __restrict__ L1,
    unsigned* __restrict__ H2, unsigned* __restrict__ L2,
    int mode)
{
    const float* W    = (blockIdx.z == 0) ? W0  : (blockIdx.z == 1) ? W1  : W2;
    const float* bias = (blockIdx.z == 0) ? b0p : (blockIdx.z == 1) ? b1p : b2p;

    __shared__ float sA[128][36];
    __shared__ float sB[64][36];

    const int tid  = threadIdx.x;
    const int lane = tid & 31;
    const int wid  = tid >> 5;
    const int gID  = lane >> 2;
    const int tIG  = lane & 3;
    const int wm   = (wid >> 1) * 32;
    const int wn   = (wid & 1) * 32;
    const int m0   = blockIdx.y * 128;
    const int n0   = blockIdx.x * 64;

    float d[2][4][4];
#pragma unroll
    for (int mi = 0; mi < 2; ++mi)
#pragma unroll
        for (int ni = 0; ni < 4; ++ni)
#pragma unroll
            for (int r = 0; r < 4; ++r) d[mi][ni][r] = 0.f;

    for (int k0 = 0; k0 < 512; k0 += 32) {
#pragma unroll
        for (int i = 0; i < 4; ++i) {
            int j = tid + i * 256;
            int row = j >> 3, c = (j & 7) * 4;
            *(float4*)&sA[row][c] = *(const float4*)(A + (size_t)(m0 + row) * 512 + k0 + c);
        }
#pragma unroll
        for (int i = 0; i < 2; ++i) {
            int j = tid + i * 256;
            int row = j >> 3, c = (j & 7) * 4;
            *(float4*)&sB[row][c] = *(const float4*)(W + (size_t)(n0 + row) * 512 + k0 + c);
        }
        __syncthreads();

#pragma unroll
        for (int ks = 0; ks < 4; ++ks) {
            unsigned bh[4][2], bl[4][2];
#pragma unroll
            for (int ni = 0; ni < 4; ++ni) {
                split_tf32(sB[wn + ni * 8 + gID][ks * 8 + tIG],     bh[ni][0], bl[ni][0]);
                split_tf32(sB[wn + ni * 8 + gID][ks * 8 + tIG + 4], bh[ni][1], bl[ni][1]);
            }
#pragma unroll
            for (int mi = 0; mi < 2; ++mi) {
                unsigned ah[4], al[4];
                split_tf32(sA[wm + mi * 16 + gID    ][ks * 8 + tIG],     ah[0], al[0]);
                split_tf32(sA[wm + mi * 16 + gID + 8][ks * 8 + tIG],     ah[1], al[1]);
                split_tf32(sA[wm + mi * 16 + gID    ][ks * 8 + tIG + 4], ah[2], al[2]);
                split_tf32(sA[wm + mi * 16 + gID + 8][ks * 8 + tIG + 4], ah[3], al[3]);
#pragma unroll
                for (int ni = 0; ni < 4; ++ni) {
                    mma_tf32(d[mi][ni], ah, bh[ni][0], bh[ni][1]);
                    mma_tf32(d[mi][ni], ah, bl[ni][0], bl[ni][1]);
                    mma_tf32(d[mi][ni], al, bh[ni][0], bh[ni][1]);
                }
            }
        }
        __syncthreads();
    }

    if (mode == 1) {
#pragma unroll
        for (int mi = 0; mi < 2; ++mi) {
#pragma unroll
            for (int ni = 0; ni < 4; ++ni) {
                const int row = m0 + wm + mi * 16 + gID;
                const int col = n0 + wn + ni * 8 + 2 * tIG;
                float2 bb = *(const float2*)&bias[col];
                float2 o0 = make_float2(d[mi][ni][0] + bb.x, d[mi][ni][1] + bb.y);
                float2 o1 = make_float2(d[mi][ni][2] + bb.x, d[mi][ni][3] + bb.y);
                *(float2*)&C[(size_t)row * 512 + col]       = o0;
                *(float2*)&C[(size_t)(row + 8) * 512 + col] = o1;
            }
        }
    } else {
        unsigned* H = (blockIdx.z == 0) ? H0 : (blockIdx.z == 1) ? H1 : H2;
        unsigned* L = (blockIdx.z == 0) ? L0 : (blockIdx.z == 1) ? L1 : L2;
        const float scale = (blockIdx.z == 0) ? 0.125f : 1.0f;  // fold 1/sqrt(HD) into Q
#pragma unroll
        for (int mi = 0; mi < 2; ++mi) {
#pragma unroll
            for (int ni = 0; ni < 4; ++ni) {
                const int row = m0 + wm + mi * 16 + gID;
                const int col = n0 + wn + ni * 8 + 2 * tIG;
                float2 bb = *(const float2*)&bias[col];
                float v00 = (d[mi][ni][0] + bb.x) * scale;
                float v01 = (d[mi][ni][1] + bb.y) * scale;
                float v10 = (d[mi][ni][2] + bb.x) * scale;
                float v11 = (d[mi][ni][3] + bb.y) * scale;
                uint2 h0, l0, h1, l1;
                split_tf32(v00, h0.x, l0.x); split_tf32(v01, h0.y, l0.y);
                split_tf32(v10, h1.x, l1.x); split_tf32(v11, h1.y, l1.y);
                *(uint2*)&H[(size_t)row * 512 + col]       = h0;
                *(uint2*)&L[(size_t)row * 512 + col]       = l0;
                *(uint2*)&H[(size_t)(row + 8) * 512 + col] = h1;
                *(uint2*)&L[(size_t)(row + 8) * 512 + col] = l1;
            }
        }
    }
}

// ============================================================================
// Edge bias (coalesced, smem-staged) — validated R6/R7.
// ============================================================================
__global__ __launch_bounds__(256) void edge_bias_kernel(
    const float4* __restrict__ ef4, const int* __restrict__ mask,
    const float* __restrict__ We, const float* __restrict__ be,
    float* __restrict__ bias)
{
    __shared__ float sE[256 * 33];
    __shared__ unsigned long long sW2[EE][4];
    __shared__ float sbe[HH];

    const int t = threadIdx.x;
    if (t < EE * 4) {
        int e = t >> 2, p = t & 3;
        sW2[e][p] = pk2(We[(2 * p) * EE + e], We[(2 * p + 1) * EE + e]);
    }
    if (t < HH) sbe[t] = be[t];

    const size_t row0 = (size_t)blockIdx.x * 256;
    const size_t base4 = row0 * 8;

#pragma unroll
    for (int i = 0; i < 8; ++i) {
        int j = t + i * 256;
        float4 v = ef4[base4 + j];
        float* dst = &sE[(j >> 3) * 33 + (j & 7) * 4];
        dst[0] = v.x; dst[1] = v.y; dst[2] = v.z; dst[3] = v.w;
    }
    __syncthreads();

    const int mk = mask[row0 + t];

    unsigned long long acc[4];
#pragma unroll
    for (int p = 0; p < 4; ++p) acc[p] = pk2(sbe[2 * p], sbe[2 * p + 1]);

    const float* myrow = &sE[t * 33];
#pragma unroll
    for (int e = 0; e < EE; ++e) {
        float v = myrow[e];
        unsigned long long v2 = pk2(v, v);
#pragma unroll
        for (int p = 0; p < 4; ++p) acc[p] = fma2(v2, sW2[e][p], acc[p]);
    }

    const size_t kq = row0 + t;
    const int k = (int)(kq & (NN - 1));
    const size_t bq = kq >> 10;
    const int q = (int)(bq & (NN - 1));
    const int b = (int)(bq >> 10);

#pragma unroll
    for (int p = 0; p < 4; ++p) {
        float2 o = upk2(acc[p]);
        float o0 = mk ? o.x : -1e30f;
        float o1 = mk ? o.y : -1e30f;
        bias[(((size_t)b * HH + 2 * p    ) * NN + q) * NN + k] = o0;
        bias[(((size_t)b * HH + 2 * p + 1) * NN + q) * NN + k] = o1;
    }
}

// ============================================================================
// Flash attention, 3xTF32 mma with PRE-SPLIT operands.
// CTA = (64 q, head, batch); 4 warps; warp owns 16 q-rows.
// Key-tile = 32. Q fragments in registers (loaded once). Smem: K hi/lo
// [32][68], Vt hi/lo [64][36], P hi/lo [64][36] (own region -> 2 syncs/tile).
// ============================================================================
#define KTILE 32
#define KST 68
#define PST 36
#define SMEM_ATTN ((2*KTILE*KST + 4*64*PST) * 4)   // 54272 bytes

__global__ __launch_bounds__(128, 3) void attn_mma(
    const unsigned* __restrict__ Qh, const unsigned* __restrict__ Ql,
    const unsigned* __restrict__ Kh, const unsigned* __restrict__ Kl,
    const unsigned* __restrict__ Vh, const unsigned* __restrict__ Vl,
    const float* __restrict__ bias, float* __restrict__ AO)
{
    extern __shared__ unsigned smu[];
    unsigned* sKh = smu;                    // [32][KST]
    unsigned* sKl = sKh + KTILE * KST;
    unsigned* sVh = sKl + KTILE * KST;      // Vt: [64 d][PST]
    unsigned* sVl = sVh + 64 * PST;
    unsigned* sPh = sVl + 64 * PST;         // P: [64 q][PST]
    unsigned* sPl = sPh + 64 * PST;

    const int tid  = threadIdx.x;
    const int lane = tid & 31;
    const int wid  = tid >> 5;
    const int gID  = lane >> 2;
    const int tIG  = lane & 3;
    const int wq   = wid * 16;
    const int q0   = blockIdx.x * 64;
    const int h    = blockIdx.y;
    const int b    = blockIdx.z;

    const int rowA = wq + gID;
    const int rowB = wq + gID + 8;

    // ---- Q fragments in registers (Q pre-scaled & pre-split) ----
    unsigned qh[8][4], ql[8][4];
    {
        const size_t rA = (size_t)(b * NN + q0 + rowA) * FF + h * HD;
        const size_t rB = (size_t)(b * NN + q0 + rowB) * FF + h * HD;
#pragma unroll
        for (int ks = 0; ks < 8; ++ks) {
            const int c = ks * 8 + tIG;
            qh[ks][0] = Qh[rA + c];     qh[ks][1] = Qh[rB + c];
            qh[ks][2] = Qh[rA + c + 4]; qh[ks][3] = Qh[rB + c + 4];
            ql[ks][0] = Ql[rA + c];     ql[ks][1] = Ql[rB + c];
            ql[ks][2] = Ql[rA + c + 4]; ql[ks][3] = Ql[rB + c + 4];
        }
    }

    const float* biasb = bias + ((size_t)b * HH + h) * NN * NN;

    float m0 = -1e38f, m1 = -1e38f, l0 = 0.f, l1 = 0.f;
    float oacc[8][4];
#pragma unroll
    for (int ni = 0; ni < 8; ++ni)
#pragma unroll
        for (int r = 0; r < 4; ++r) oacc[ni][r] = 0.f;

    const int lr  = tid >> 2;          // 0..31 load row
    const int lc0 = (tid & 3) * 16;    // load col base

    for (int kt = 0; kt < NN; kt += KTILE) {
        __syncthreads();   // prior tile's K/V reads fully retired
        // ---- load K tile [key][d] hi/lo, V tile transposed [d][key] hi/lo ----
        {
            const size_t go = (size_t)(b * NN + kt + lr) * FF + h * HD + lc0;
#pragma unroll
            for (int u = 0; u < 4; ++u) {
                *(uint4*)&sKh[lr * KST + lc0 + 4 * u] = *(const uint4*)(Kh + go + 4 * u);
                *(uint4*)&sKl[lr * KST + lc0 + 4 * u] = *(const uint4*)(Kl + go + 4 * u);
            }
            unsigned th[16], tl[16];
#pragma unroll
            for (int u = 0; u < 4; ++u) {
                *(uint4*)&th[4 * u] = *(const uint4*)(Vh + go + 4 * u);
                *(uint4*)&tl[4 * u] = *(const uint4*)(Vl + go + 4 * u);
            }
#pragma unroll
            for (int cc = 0; cc < 16; ++cc) {
                sVh[(lc0 + cc) * PST + lr] = th[cc];
                sVl[(lc0 + cc) * PST + lr] = tl[cc];
            }
        }
        __syncthreads();

        // ---- S = Q K^T (A in regs, B pre-split in smem) ----
        float sacc[4][4];
#pragma unroll
        for (int ni = 0; ni < 4; ++ni)
#pragma unroll
            for (int r = 0; r < 4; ++r) sacc[ni][r] = 0.f;

#pragma unroll
        for (int ks = 0; ks < 8; ++ks) {
#pragma unroll
            for (int ni = 0; ni < 4; ++ni) {
                const int broff = (ni * 8 + gID) * KST + ks * 8 + tIG;
                unsigned bh0 = sKh[broff], bh1 = sKh[broff + 4];
                unsigned bl0 = sKl[broff], bl1 = sKl[broff + 4];
                mma_tf32(sacc[ni], qh[ks], bh0, bh1);
                mma_tf32(sacc[ni], qh[ks], bl0, bl1);
                mma_tf32(sacc[ni], ql[ks], bh0, bh1);
            }
        }

        // ---- bias + online softmax (Q already carries 1/8 scale) ----
        const float* br0 = biasb + (size_t)(q0 + rowA) * NN + kt;
        const float* br1 = biasb + (size_t)(q0 + rowB) * NN + kt;
        float mx0 = -1e38f, mx1 = -1e38f;
#pragma unroll
        for (int ni = 0; ni < 4; ++ni) {
            float2 b0v = *(const float2*)&br0[ni * 8 + 2 * tIG];
            float2 b1v = *(const float2*)&br1[ni * 8 + 2 * tIG];
            sacc[ni][0] += b0v.x;
            sacc[ni][1] += b0v.y;
            sacc[ni][2] += b1v.x;
            sacc[ni][3] += b1v.y;
            mx0 = fmaxf(mx0, fmaxf(sacc[ni][0], sacc[ni][1]));
            mx1 = fmaxf(mx1, fmaxf(sacc[ni][2], sacc[ni][3]));
        }
        mx0 = fmaxf(mx0, __shfl_xor_sync(0xffffffffu, mx0, 1));
        mx0 = fmaxf(mx0, __shfl_xor_sync(0xffffffffu, mx0, 2));
        mx1 = fmaxf(mx1, __shfl_xor_sync(0xffffffffu, mx1, 1));
        mx1 = fmaxf(mx1, __shfl_xor_sync(0xffffffffu, mx1, 2));

        const float mn0 = fmaxf(m0, mx0), mn1 = fmaxf(m1, mx1);
        const float c0f = __expf(m0 - mn0), c1f = __expf(m1 - mn1);
        m0 = mn0; m1 = mn1;

        float ps0 = 0.f, ps1 = 0.f;
#pragma unroll
        for (int ni = 0; ni < 4; ++ni) {
            sacc[ni][0] = __expf(sacc[ni][0] - mn0); ps0 += sacc[ni][0];
            sacc[ni][1] = __expf(sacc[ni][1] - mn0); ps0 += sacc[ni][1];
            sacc[ni][2] = __expf(sacc[ni][2] - mn1); ps1 += sacc[ni][2];
            sacc[ni][3] = __expf(sacc[ni][3] - mn1); ps1 += sacc[ni][3];
        }
        ps0 += __shfl_xor_sync(0xffffffffu, ps0, 1);
        ps0 += __shfl_xor_sync(0xffffffffu, ps0, 2);
        ps1 += __shfl_xor_sync(0xffffffffu, ps1, 1);
        ps1 += __shfl_xor_sync(0xffffffffu, ps1, 2);
        l0 = l0 * c0f + ps0;
        l1 = l1 * c1f + ps1;

#pragma unroll
        for (int ni = 0; ni < 8; ++ni) {
            oacc[ni][0] *= c0f; oacc[ni][1] *= c0f;
            oacc[ni][2] *= c1f; oacc[ni][3] *= c1f;
        }

        // ---- split P once, write hi/lo to own smem region (warp-private) ----
#pragma unroll
        for (int ni = 0; ni < 4; ++ni) {
            uint2 h0v, l0v, h1v, l1v;
            split_tf32(sacc[ni][0], h0v.x, l0v.x); split_tf32(sacc[ni][1], h0v.y, l0v.y);
            split_tf32(sacc[ni][2], h1v.x, l1v.x); split_tf32(sacc[ni][3], h1v.y, l1v.y);
            *(uint2*)&sPh[rowA * PST + ni * 8 + 2 * tIG] = h0v;
            *(uint2*)&sPl[rowA * PST + ni * 8 + 2 * tIG] = l0v;
            *(uint2*)&sPh[rowB * PST + ni * 8 + 2 * tIG] = h1v;
            *(uint2*)&sPl[rowB * PST + ni * 8 + 2 * tIG] = l1v;
        }
        __syncwarp();

        // ---- O += P V (A = P hi/lo from smem, B = Vt hi/lo from smem) ----
#pragma unroll
        for (int ks = 0; ks < 4; ++ks) {
            const int pa = rowA * PST + ks * 8 + tIG;
            const int pb = rowB * PST + ks * 8 + tIG;
            unsigned ph[4] = { sPh[pa], sPh[pb], sPh[pa + 4], sPh[pb + 4] };
            unsigned pl[4] = { sPl[pa], sPl[pb], sPl[pa + 4], sPl[pb + 4] };
#pragma unroll
            for (int ni = 0; ni < 8; ++ni) {
                const int vo = (ni * 8 + gID) * PST + ks * 8 + tIG;
                unsigned bh0 = sVh[vo], bh1 = sVh[vo + 4];
                unsigned bl0 = sVl[vo], bl1 = sVl[vo + 4];
                mma_tf32(oacc[ni], ph, bh0, bh1);
                mma_tf32(oacc[ni], ph, bl0, bl1);
                mma_tf32(oacc[ni], pl, bh0, bh1);
            }
        }
    }

    // ---- epilogue: normalize, write [b, q, h*64 + d] ----
    const float i0 = 1.0f / l0, i1 = 1.0f / l1;
    float* o0 = AO + (size_t)(b * NN + q0 + rowA) * FF + h * HD;
    float* o1 = AO + (size_t)(b * NN + q0 + rowB) * FF + h * HD;
#pragma unroll
    for (int ni = 0; ni < 8; ++ni) {
        *(float2*)&o0[ni * 8 + 2 * tIG] = make_float2(oacc[ni][0] * i0, oacc[ni][1] * i0);
        *(float2*)&o1[ni * 8 + 2 * tIG] = make_float2(oacc[ni][2] * i1, oacc[ni][3] * i1);
    }
}

// ============================================================================
// Launch
// ============================================================================
extern "C" void kernel_launch(void* const* d_in, const int* in_sizes, int n_in,
                              void* d_out, int out_size)
{
    (void)in_sizes; (void)n_in; (void)out_size;
    const float* x   = (const float*)d_in[0];
    const float* ef  = (const float*)d_in[1];
    const int*   msk = (const int*)  d_in[2];
    const float* Wq  = (const float*)d_in[3];
    const float* bq  = (const float*)d_in[4];
    const float* Wk  = (const float*)d_in[5];
    const float* bk  = (const float*)d_in[6];
    const float* Wv  = (const float*)d_in[7];
    const float* bv  = (const float*)d_in[8];
    const float* We  = (const float*)d_in[9];
    const float* be  = (const float*)d_in[10];
    const float* Wo  = (const float*)d_in[11];
    const float* bo  = (const float*)d_in[12];
    float* out = (float*)d_out;

    unsigned *pQh, *pQl, *pKh, *pKl, *pVh, *pVl;
    float *pAO, *pBias;
    cudaGetSymbolAddress((void**)&pQh,   g_Qh);
    cudaGetSymbolAddress((void**)&pQl,   g_Ql);
    cudaGetSymbolAddress((void**)&pKh,   g_Kh);
    cudaGetSymbolAddress((void**)&pKl,   g_Kl);
    cudaGetSymbolAddress((void**)&pVh,   g_Vh);
    cudaGetSymbolAddress((void**)&pVl,   g_Vl);
    cudaGetSymbolAddress((void**)&pAO,   g_AO);
    cudaGetSymbolAddress((void**)&pBias, g_bias);

    static int smem_set = 0;
    if (!smem_set) {
        cudaFuncSetAttribute(attn_mma, cudaFuncAttributeMaxDynamicSharedMemorySize,
                             SMEM_ATTN);
        smem_set = 1;
    }

    // QKV fused (mode 0: split outputs; Q pre-scaled by 0.125)
    dim3 gqkv(512 / 64, MM / 128, 3);
    gemm_tf32x3<<<gqkv, 256>>>(x, Wq, Wk, Wv, bq, bk, bv,
                               nullptr, pQh, pQl, pKh, pKl, pVh, pVl, 0);

    edge_bias_kernel<<<(BB * NN * NN) / 256, 256>>>(
        (const float4*)ef, msk, We, be, pBias);

    attn_mma<<<dim3(NN / 64, HH, BB), 128, SMEM_ATTN>>>(
        pQh, pQl, pKh, pKl, pVh, pVl, pBias, pAO);

    // O-projection (mode 1: float output)
    dim3 go(512 / 64, MM / 128, 1);
    gemm_tf32x3<<<go, 256>>>(pAO, Wo, Wo, Wo, bo, bo, bo,
                             out, nullptr, nullptr, nullptr, nullptr, nullptr, nullptr, 1);
}